// round 16
// baseline (speedup 1.0000x reference)
#include <cuda_runtime.h>
#include <cuda_bf16.h>
#include <math.h>
#include <stdint.h>

#define HEADS    16
#define HEAD_DIM 64
#define DIM      1024
#define INNER    1024
#define BATCH    2
#define SEQ      2048
#define ROWS     4096
#define QKV_N    3072

// ---------------- scratch (no allocs allowed) ----------------
__device__ float         g_res[(size_t)ROWS * DIM];
__device__ __nv_bfloat16 g_ahi[(size_t)ROWS * DIM];
__device__ __nv_bfloat16 g_alo[(size_t)ROWS * DIM];
__device__ __nv_bfloat16 g_bhi[(size_t)QKV_N * DIM];
__device__ __nv_bfloat16 g_blo[(size_t)QKV_N * DIM];
__device__ __nv_bfloat16 g_qhi[(size_t)ROWS * DIM];
__device__ __nv_bfloat16 g_qlo[(size_t)ROWS * DIM];
__device__ __nv_bfloat16 g_khi[(size_t)ROWS * DIM];
__device__ __nv_bfloat16 g_klo[(size_t)ROWS * DIM];
__device__ __nv_bfloat16 g_vthi[(size_t)ROWS * DIM];
__device__ __nv_bfloat16 g_vtlo[(size_t)ROWS * DIM];

// ---------------- PTX helpers ----------------
__device__ __forceinline__ uint32_t smem_u32(const void* p) {
    uint32_t a;
    asm("{ .reg .u64 t; cvta.to.shared.u64 t, %1; cvt.u32.u64 %0, t; }" : "=r"(a) : "l"(p));
    return a;
}
__device__ __forceinline__ void cp16(uint32_t s, const void* g) {
    asm volatile("cp.async.cg.shared.global [%0], [%1], 16;" :: "r"(s), "l"(g));
}
#define CP_COMMIT() asm volatile("cp.async.commit_group;" ::: "memory")
#define CP_WAIT(n)  asm volatile("cp.async.wait_group %0;" :: "n"(n) : "memory")

__device__ __forceinline__ void ldsm4(uint32_t& r0, uint32_t& r1, uint32_t& r2, uint32_t& r3,
                                      uint32_t a) {
    asm volatile("ldmatrix.sync.aligned.m8n8.x4.shared.b16 {%0,%1,%2,%3}, [%4];"
                 : "=r"(r0), "=r"(r1), "=r"(r2), "=r"(r3) : "r"(a));
}
__device__ __forceinline__ void mma16816(float* d, const uint32_t* a, uint32_t b0, uint32_t b1) {
    asm volatile(
        "mma.sync.aligned.m16n8k16.row.col.f32.bf16.bf16.f32 "
        "{%0,%1,%2,%3}, {%4,%5,%6,%7}, {%8,%9}, {%0,%1,%2,%3};"
        : "+f"(d[0]), "+f"(d[1]), "+f"(d[2]), "+f"(d[3])
        : "r"(a[0]), "r"(a[1]), "r"(a[2]), "r"(a[3]), "r"(b0), "r"(b1));
}
__device__ __forceinline__ void split2(float a, float b, uint32_t& hi, uint32_t& lo) {
    __nv_bfloat16 ha = __float2bfloat16(a), hb = __float2bfloat16(b);
    __nv_bfloat162 H; H.x = ha; H.y = hb;
    __nv_bfloat162 L;
    L.x = __float2bfloat16(a - __bfloat162float(ha));
    L.y = __float2bfloat16(b - __bfloat162float(hb));
    hi = *(uint32_t*)&H;
    lo = *(uint32_t*)&L;
}

// ---------------------------------------------------------------------------
// Prep kernels
// ---------------------------------------------------------------------------
__global__ __launch_bounds__(256) void split_fp32(
    const float* __restrict__ X, __nv_bfloat16* __restrict__ H,
    __nv_bfloat16* __restrict__ L, int n4)
{
    int i = blockIdx.x * 256 + threadIdx.x;
    if (i >= n4) return;
    float4 v = ((const float4*)X)[i];
    union { __nv_bfloat16 b[4]; uint2 u; } ph, pl;
    float f[4] = {v.x, v.y, v.z, v.w};
#pragma unroll
    for (int j = 0; j < 4; j++) {
        __nv_bfloat16 h = __float2bfloat16(f[j]);
        ph.b[j] = h;
        pl.b[j] = __float2bfloat16(f[j] - __bfloat162float(h));
    }
    ((uint2*)H)[i] = ph.u;
    ((uint2*)L)[i] = pl.u;
}

__global__ void tsplit(const float* __restrict__ W, __nv_bfloat16* __restrict__ TH,
                       __nv_bfloat16* __restrict__ TL, int K, int N)
{
    __shared__ float t[32][33];
    int n0 = blockIdx.x * 32, k0 = blockIdx.y * 32;
    int tx = threadIdx.x, ty = threadIdx.y;
#pragma unroll
    for (int i = 0; i < 32; i += 8)
        t[ty + i][tx] = W[(size_t)(k0 + ty + i) * N + n0 + tx];
    __syncthreads();
#pragma unroll
    for (int i = 0; i < 32; i += 8) {
        float v = t[tx][ty + i];
        __nv_bfloat16 h = __float2bfloat16(v);
        size_t oidx = (size_t)(n0 + ty + i) * K + k0 + tx;
        TH[oidx] = h;
        TL[oidx] = __float2bfloat16(v - __bfloat162float(h));
    }
}

// ---------------------------------------------------------------------------
// mma.sync bf16x3 GEMM. 512 threads, 16 warps of 32x32 (4x4 grid).
// 3-stage cp.async, ONE barrier per chunk. Natural regs (no min-blocks bound).
// mode 0: fp32 C (+bias +resid). mode 1: fused qkv split epilogue.
// ---------------------------------------------------------------------------
#define BM 128
#define BN 128
#define BKC 32
#define ROWB 80
#define TILE_BYTES (128 * ROWB)
#define STAGE_BYTES (4 * TILE_BYTES)          // 40960
#define GEMM_SMEM (3 * STAGE_BYTES + 256)     // 123136

__global__ __launch_bounds__(512) void gemm_mma(
    const __nv_bfloat16* __restrict__ Ahi, const __nv_bfloat16* __restrict__ Alo,
    const __nv_bfloat16* __restrict__ Bhi, const __nv_bfloat16* __restrict__ Blo,
    float* __restrict__ C, int K, int N,
    const float* __restrict__ bias, const float* __restrict__ resid,
    int mode,
    __nv_bfloat16* __restrict__ qhi, __nv_bfloat16* __restrict__ qlo,
    __nv_bfloat16* __restrict__ khi, __nv_bfloat16* __restrict__ klo,
    __nv_bfloat16* __restrict__ vthi, __nv_bfloat16* __restrict__ vtlo)
{
    extern __shared__ char dsm[];
    const int tid  = threadIdx.x;
    const int wid  = tid >> 5;
    const int lane = tid & 31;
    const int bm   = blockIdx.y * BM;
    const int bn   = blockIdx.x * BN;

    const uint32_t sb = (smem_u32(dsm) + 127u) & ~127u;

    // loader: 512 chunks per tile, 1 chunk per thread per tile
    const int r0 = tid >> 2, c0 = tid & 3;
    const uint32_t s0 = r0 * ROWB + c0 * 16;
    const size_t gA0 = (size_t)(bm + r0) * K + c0 * 8;
    const size_t gB0 = (size_t)(bn + r0) * K + c0 * 8;

    float acc[2][4][4];
#pragma unroll
    for (int i = 0; i < 2; i++)
#pragma unroll
        for (int j = 0; j < 4; j++)
#pragma unroll
            for (int q = 0; q < 4; q++) acc[i][j][q] = 0.f;

    const int nch = K / BKC;

#define LOAD_STAGE(kc, st) do {                                                 \
    uint32_t s = sb + (uint32_t)(st) * STAGE_BYTES;                             \
    int ko = (kc) * BKC;                                                        \
    cp16(s + s0,                  Ahi + gA0 + ko);                              \
    cp16(s + TILE_BYTES + s0,     Alo + gA0 + ko);                              \
    cp16(s + 2 * TILE_BYTES + s0, Bhi + gB0 + ko);                              \
    cp16(s + 3 * TILE_BYTES + s0, Blo + gB0 + ko);                              \
} while (0)

    LOAD_STAGE(0, 0);
    CP_COMMIT();
    if (nch > 1) { LOAD_STAGE(1, 1); CP_COMMIT(); }

    const int wm = (wid & 3) * 32;        // 4x4 warp grid
    const int wn = (wid >> 2) * 32;

    const uint32_t a_off = (uint32_t)(wm + (lane & 15)) * ROWB + ((lane >> 4) << 3) * 2;
    const uint32_t b_off = (uint32_t)(wn + (lane & 7) + ((lane >> 4) << 3)) * ROWB +
                           (((lane >> 3) & 1) << 3) * 2;

    for (int kc = 0; kc < nch; kc++) {
        const int st = kc % 3;
        if (kc + 1 < nch) { CP_WAIT(1); } else { CP_WAIT(0); }
        __syncthreads();
        if (kc + 2 < nch) { LOAD_STAGE(kc + 2, (kc + 2) % 3); CP_COMMIT(); }

        const uint32_t sAhi = sb + (uint32_t)st * STAGE_BYTES;
        const uint32_t sAlo = sAhi + TILE_BYTES;
        const uint32_t sBhi = sAhi + 2 * TILE_BYTES;
        const uint32_t sBlo = sAhi + 3 * TILE_BYTES;

#pragma unroll
        for (int ks = 0; ks < 2; ks++) {
            const uint32_t kb = ks * 32;
            uint32_t ah[2][4], bh[8];
#pragma unroll
            for (int mf = 0; mf < 2; mf++)
                ldsm4(ah[mf][0], ah[mf][1], ah[mf][2], ah[mf][3],
                      sAhi + a_off + kb + mf * (16 * ROWB));
            ldsm4(bh[0], bh[1], bh[2], bh[3], sBhi + b_off + kb);
            ldsm4(bh[4], bh[5], bh[6], bh[7], sBhi + b_off + kb + 16 * ROWB);
#pragma unroll
            for (int mf = 0; mf < 2; mf++)
#pragma unroll
                for (int nf = 0; nf < 4; nf++)
                    mma16816(acc[mf][nf], ah[mf], bh[nf * 2], bh[nf * 2 + 1]);
            {
                uint32_t al[2][4];
#pragma unroll
                for (int mf = 0; mf < 2; mf++)
                    ldsm4(al[mf][0], al[mf][1], al[mf][2], al[mf][3],
                          sAlo + a_off + kb + mf * (16 * ROWB));
#pragma unroll
                for (int mf = 0; mf < 2; mf++)
#pragma unroll
                    for (int nf = 0; nf < 4; nf++)
                        mma16816(acc[mf][nf], al[mf], bh[nf * 2], bh[nf * 2 + 1]);
            }
            {
                uint32_t bl[8];
                ldsm4(bl[0], bl[1], bl[2], bl[3], sBlo + b_off + kb);
                ldsm4(bl[4], bl[5], bl[6], bl[7], sBlo + b_off + kb + 16 * ROWB);
#pragma unroll
                for (int mf = 0; mf < 2; mf++)
#pragma unroll
                    for (int nf = 0; nf < 4; nf++)
                        mma16816(acc[mf][nf], ah[mf], bl[nf * 2], bl[nf * 2 + 1]);
            }
        }
    }

    // ---------------- epilogue ----------------
    if (mode == 0) {
#pragma unroll
        for (int mf = 0; mf < 2; mf++) {
            const int row = bm + wm + mf * 16 + (lane >> 2);
#pragma unroll
            for (int nf = 0; nf < 4; nf++) {
                const int col = bn + wn + nf * 8 + 2 * (lane & 3);
                float2 v0 = make_float2(acc[mf][nf][0], acc[mf][nf][1]);
                float2 v1 = make_float2(acc[mf][nf][2], acc[mf][nf][3]);
                if (bias) {
                    float2 bi = *(const float2*)(bias + col);
                    v0.x += bi.x; v0.y += bi.y;
                    v1.x += bi.x; v1.y += bi.y;
                }
                if (resid) {
                    float2 ra = *(const float2*)(resid + (size_t)row * N + col);
                    float2 rb = *(const float2*)(resid + (size_t)(row + 8) * N + col);
                    v0.x += ra.x; v0.y += ra.y;
                    v1.x += rb.x; v1.y += rb.y;
                }
                *(float2*)(C + (size_t)row * N + col) = v0;
                *(float2*)(C + (size_t)(row + 8) * N + col) = v1;
            }
        }
    } else if (bn < 1024) {
        // q: scale 0.125, split -> [row][dim]
#pragma unroll
        for (int mf = 0; mf < 2; mf++) {
            const int rowa = bm + wm + mf * 16 + (lane >> 2);
#pragma unroll
            for (int nf = 0; nf < 4; nf++) {
                const int col = bn + wn + nf * 8 + 2 * (lane & 3);
                uint32_t hh, ll;
                split2(acc[mf][nf][0] * 0.125f, acc[mf][nf][1] * 0.125f, hh, ll);
                *(uint32_t*)(qhi + (size_t)rowa * DIM + col) = hh;
                *(uint32_t*)(qlo + (size_t)rowa * DIM + col) = ll;
                split2(acc[mf][nf][2] * 0.125f, acc[mf][nf][3] * 0.125f, hh, ll);
                *(uint32_t*)(qhi + (size_t)(rowa + 8) * DIM + col) = hh;
                *(uint32_t*)(qlo + (size_t)(rowa + 8) * DIM + col) = ll;
            }
        }
    } else if (bn < 2048) {
        // k: split -> [bh][key][d]
#pragma unroll
        for (int mf = 0; mf < 2; mf++) {
            const int rowa = bm + wm + mf * 16 + (lane >> 2);
            const int b0b = rowa >> 11;
#pragma unroll
            for (int nf = 0; nf < 4; nf++) {
                const int ck = bn - 1024 + wn + nf * 8 + 2 * (lane & 3);
                const int hK = ck >> 6, dK = ck & 63;
                size_t o0 = ((size_t)(b0b * HEADS + hK) << 17) + (size_t)(rowa & 2047) * 64 + dK;
                size_t o1 = ((size_t)(b0b * HEADS + hK) << 17) + (size_t)((rowa + 8) & 2047) * 64 + dK;
                uint32_t hh, ll;
                split2(acc[mf][nf][0], acc[mf][nf][1], hh, ll);
                *(uint32_t*)(khi + o0) = hh;
                *(uint32_t*)(klo + o0) = ll;
                split2(acc[mf][nf][2], acc[mf][nf][3], hh, ll);
                *(uint32_t*)(khi + o1) = hh;
                *(uint32_t*)(klo + o1) = ll;
            }
        }
    } else {
        // v: smem transpose, split -> [bh][d][key]
        float* esm = (float*)(dsm + (sb - smem_u32(dsm)));   // [128][129]
        __syncthreads();
#pragma unroll
        for (int mf = 0; mf < 2; mf++) {
            const int rl = wm + mf * 16 + (lane >> 2);
#pragma unroll
            for (int nf = 0; nf < 4; nf++) {
                const int cl = wn + nf * 8 + 2 * (lane & 3);
                esm[rl * 129 + cl]       = acc[mf][nf][0];
                esm[rl * 129 + cl + 1]   = acc[mf][nf][1];
                esm[(rl + 8) * 129 + cl]     = acc[mf][nf][2];
                esm[(rl + 8) * 129 + cl + 1] = acc[mf][nf][3];
            }
        }
        __syncthreads();
        const int bb   = bm >> 11;
        const int key0 = bm & 2047;
        const int colc = tid & 127;            // output column (head-dim pair)
        const int q4   = tid >> 7;             // key quarter (32 keys)
        const int dd   = colc & 63;
        const int hg   = ((bn - 2048) >> 6) + (colc >> 6);
        const size_t ob = ((size_t)(bb * HEADS + hg) << 17) + (size_t)dd * SEQ +
                          key0 + q4 * 32;
#pragma unroll
        for (int k = 0; k < 32; k += 2) {
            float v0 = esm[(q4 * 32 + k) * 129 + colc];
            float v1 = esm[(q4 * 32 + k + 1) * 129 + colc];
            uint32_t hh, ll;
            split2(v0, v1, hh, ll);
            *(uint32_t*)(vthi + ob + k) = hh;
            *(uint32_t*)(vtlo + ob + k) = ll;
        }
    }
#undef LOAD_STAGE
}

// ---------------------------------------------------------------------------
// Flash attention, mma.sync bf16 split. 2-stage, 2 barriers/tile, 2 CTAs/SM.
// (byte-identical behavior to the R14 passing version)
// ---------------------------------------------------------------------------
#define AT_ROWB  144
#define AT_TILE  (64 * AT_ROWB)       // 9216
#define AT_STAGE (4 * AT_TILE)        // 36864
#define AT_SMEM  (2 * AT_STAGE + 128) // 73856

__global__ __launch_bounds__(256, 2) void attn_mma(
    const __nv_bfloat16* __restrict__ qhi, const __nv_bfloat16* __restrict__ qlo,
    const __nv_bfloat16* __restrict__ khi, const __nv_bfloat16* __restrict__ klo,
    const __nv_bfloat16* __restrict__ vthi, const __nv_bfloat16* __restrict__ vtlo,
    __nv_bfloat16* __restrict__ ohi, __nv_bfloat16* __restrict__ olo)
{
    extern __shared__ char dsm[];
    const int tid  = threadIdx.x;
    const int wid  = tid >> 5;
    const int lane = tid & 31;
    const int g    = lane >> 2;
    const int t    = lane & 3;
    const int bh   = blockIdx.y;
    const int b    = bh >> 4;
    const int h    = bh & 15;
    const int row0 = b * SEQ + blockIdx.x * 128;

    const uint32_t sb = (smem_u32(dsm) + 127u) & ~127u;

    // ---- stage Q, load frags ----
    {
        const uint32_t sQhi = sb, sQlo = sb + 128 * AT_ROWB;
#pragma unroll
        for (int i = 0; i < 4; i++) {
            int c = tid + i * 256;
            int r = c >> 3, ch = c & 7;
            size_t gq = (size_t)(row0 + r) * DIM + h * 64 + ch * 8;
            cp16(sQhi + r * AT_ROWB + ch * 16, qhi + gq);
            cp16(sQlo + r * AT_ROWB + ch * 16, qlo + gq);
        }
        CP_COMMIT();
        CP_WAIT(0);
        __syncthreads();
    }
    uint32_t qh[4][4], ql[4][4];
    {
        const uint32_t qoff = (uint32_t)(wid * 16 + (lane & 15)) * AT_ROWB +
                              ((lane >> 4) << 3) * 2;
#pragma unroll
        for (int ks = 0; ks < 4; ks++) {
            ldsm4(qh[ks][0], qh[ks][1], qh[ks][2], qh[ks][3], sb + qoff + ks * 32);
            ldsm4(ql[ks][0], ql[ks][1], ql[ks][2], ql[ks][3],
                  sb + 128 * AT_ROWB + qoff + ks * 32);
        }
    }
    __syncthreads();

    float o[8][4];
#pragma unroll
    for (int i = 0; i < 8; i++)
#pragma unroll
        for (int j = 0; j < 4; j++) o[i][j] = 0.f;
    float m0 = -1e30f, m1 = -1e30f, l0 = 0.f, l1 = 0.f;

    const __nv_bfloat16* kb_hi = khi + ((size_t)bh << 17);
    const __nv_bfloat16* kb_lo = klo + ((size_t)bh << 17);
    const __nv_bfloat16* vb_hi = vthi + ((size_t)bh << 17);
    const __nv_bfloat16* vb_lo = vtlo + ((size_t)bh << 17);

#define LOADKV(kt, st) do {                                                     \
    uint32_t s = sb + (uint32_t)(st) * AT_STAGE;                                \
    int key0 = (kt) * 64;                                                       \
    _Pragma("unroll")                                                           \
    for (int i = 0; i < 2; i++) {                                               \
        int c = tid + i * 256;                                                  \
        int r = c >> 3, ch = c & 7;                                             \
        uint32_t so = r * AT_ROWB + ch * 16;                                    \
        cp16(s + so,               kb_hi + (size_t)(key0 + r) * 64 + ch * 8);   \
        cp16(s + AT_TILE + so,     kb_lo + (size_t)(key0 + r) * 64 + ch * 8);   \
        cp16(s + 2 * AT_TILE + so, vb_hi + (size_t)r * SEQ + key0 + ch * 8);    \
        cp16(s + 3 * AT_TILE + so, vb_lo + (size_t)r * SEQ + key0 + ch * 8);    \
    }                                                                           \
} while (0)

    const uint32_t boff = (uint32_t)((lane & 7) + ((lane >> 4) << 3)) * AT_ROWB +
                          (((lane >> 3) & 1) << 3) * 2;

    LOADKV(0, 0);
    CP_COMMIT();

    const int NT = SEQ / 64;
    for (int kt = 0; kt < NT; kt++) {
        const int st = kt & 1;
        __syncthreads();                 // readers of stage st^1 finished
        if (kt + 1 < NT) {
            LOADKV(kt + 1, st ^ 1);
            CP_COMMIT();
            CP_WAIT(1);
        } else {
            CP_WAIT(0);
        }
        __syncthreads();                 // stage st ready

        const uint32_t sKh = sb + (uint32_t)st * AT_STAGE;
        const uint32_t sKl = sKh + AT_TILE;
        const uint32_t sVh = sKh + 2 * AT_TILE;
        const uint32_t sVl = sKh + 3 * AT_TILE;

        // ---- S = Q K^T (3-term split, JIT frags) ----
        float s[8][4];
#pragma unroll
        for (int i = 0; i < 8; i++)
#pragma unroll
            for (int j = 0; j < 4; j++) s[i][j] = 0.f;

#pragma unroll
        for (int ks = 0; ks < 4; ks++) {
#pragma unroll
            for (int kb = 0; kb < 4; kb++) {
                uint32_t kh4[4];
                ldsm4(kh4[0], kh4[1], kh4[2], kh4[3],
                      sKh + boff + kb * (16 * AT_ROWB) + ks * 32);
                mma16816(s[2 * kb],     qh[ks], kh4[0], kh4[1]);
                mma16816(s[2 * kb + 1], qh[ks], kh4[2], kh4[3]);
                mma16816(s[2 * kb],     ql[ks], kh4[0], kh4[1]);
                mma16816(s[2 * kb + 1], ql[ks], kh4[2], kh4[3]);
                uint32_t kl4[4];
                ldsm4(kl4[0], kl4[1], kl4[2], kl4[3],
                      sKl + boff + kb * (16 * AT_ROWB) + ks * 32);
                mma16816(s[2 * kb],     qh[ks], kl4[0], kl4[1]);
                mma16816(s[2 * kb + 1], qh[ks], kl4[2], kl4[3]);
            }
        }

        // ---- online softmax ----
        float mx0 = -1e30f, mx1 = -1e30f;
#pragma unroll
        for (int nf = 0; nf < 8; nf++) {
            mx0 = fmaxf(mx0, fmaxf(s[nf][0], s[nf][1]));
            mx1 = fmaxf(mx1, fmaxf(s[nf][2], s[nf][3]));
        }
        mx0 = fmaxf(mx0, __shfl_xor_sync(0xffffffffu, mx0, 1));
        mx0 = fmaxf(mx0, __shfl_xor_sync(0xffffffffu, mx0, 2));
        mx1 = fmaxf(mx1, __shfl_xor_sync(0xffffffffu, mx1, 1));
        mx1 = fmaxf(mx1, __shfl_xor_sync(0xffffffffu, mx1, 2));
        const float nm0 = fmaxf(m0, mx0), nm1 = fmaxf(m1, mx1);
        const float c0 = __expf(m0 - nm0), c1 = __expf(m1 - nm1);
#pragma unroll
        for (int nf = 0; nf < 8; nf++) {
            o[nf][0] *= c0; o[nf][1] *= c0;
            o[nf][2] *= c1; o[nf][3] *= c1;
        }
        float rs0 = 0.f, rs1 = 0.f;
#pragma unroll
        for (int nf = 0; nf < 8; nf++) {
            s[nf][0] = __expf(s[nf][0] - nm0); rs0 += s[nf][0];
            s[nf][1] = __expf(s[nf][1] - nm0); rs0 += s[nf][1];
            s[nf][2] = __expf(s[nf][2] - nm1); rs1 += s[nf][2];
            s[nf][3] = __expf(s[nf][3] - nm1); rs1 += s[nf][3];
        }
        rs0 += __shfl_xor_sync(0xffffffffu, rs0, 1);
        rs0 += __shfl_xor_sync(0xffffffffu, rs0, 2);
        rs1 += __shfl_xor_sync(0xffffffffu, rs1, 1);
        rs1 += __shfl_xor_sync(0xffffffffu, rs1, 2);
        l0 = l0 * c0 + rs0;
        l1 = l1 * c1 + rs1;
        m0 = nm0; m1 = nm1;

        // ---- O += P V (3-term split, JIT frags) ----
#pragma unroll
        for (int kk = 0; kk < 4; kk++) {
            uint32_t ph[4], pl[4];
            split2(s[2 * kk][0],     s[2 * kk][1],     ph[0], pl[0]);
            split2(s[2 * kk][2],     s[2 * kk][3],     ph[1], pl[1]);
            split2(s[2 * kk + 1][0], s[2 * kk + 1][1], ph[2], pl[2]);
            split2(s[2 * kk + 1][2], s[2 * kk + 1][3], ph[3], pl[3]);

#pragma unroll
            for (int db = 0; db < 4; db++) {
                uint32_t vh4[4];
                ldsm4(vh4[0], vh4[1], vh4[2], vh4[3],
                      sVh + boff + db * (16 * AT_ROWB) + kk * 32);
                mma16816(o[2 * db],     ph, vh4[0], vh4[1]);
                mma16816(o[2 * db + 1], ph, vh4[2], vh4[3]);
                mma16816(o[2 * db],     pl, vh4[0], vh4[1]);
                mma16816(o[2 * db + 1], pl, vh4[2], vh4[3]);
                uint32_t vl4[4];
                ldsm4(vl4[0], vl4[1], vl4[2], vl4[3],
                      sVl + boff + db * (16 * AT_ROWB) + kk * 32);
                mma16816(o[2 * db],     ph, vl4[0], vl4[1]);
                mma16816(o[2 * db + 1], ph, vl4[2], vl4[3]);
            }
        }
    }
#undef LOADKV

    // ---- epilogue ----
    const float inv0 = 1.f / l0, inv1 = 1.f / l1;
    const int row_a = row0 + wid * 16 + g;
    const int row_b = row_a + 8;
#pragma unroll
    for (int nf = 0; nf < 8; nf++) {
        const int col = h * 64 + nf * 8 + 2 * t;
        uint32_t hh, ll;
        split2(o[nf][0] * inv0, o[nf][1] * inv0, hh, ll);
        *(uint32_t*)(ohi + (size_t)row_a * DIM + col) = hh;
        *(uint32_t*)(olo + (size_t)row_a * DIM + col) = ll;
        split2(o[nf][2] * inv1, o[nf][3] * inv1, hh, ll);
        *(uint32_t*)(ohi + (size_t)row_b * DIM + col) = hh;
        *(uint32_t*)(olo + (size_t)row_b * DIM + col) = ll;
    }
}

// ---------------------------------------------------------------------------
// LayerNorm
// ---------------------------------------------------------------------------
__global__ __launch_bounds__(256) void ln_kernel(
    const float* __restrict__ res, const float* __restrict__ gamma,
    const float* __restrict__ beta, float* __restrict__ out)
{
    const int row = blockIdx.x;
    const int tid = threadIdx.x;
    const float* rp = res + (size_t)row * DIM;

    float4 v = *(const float4*)(rp + tid * 4);
    float s  = v.x + v.y + v.z + v.w;
    float ss = v.x * v.x + v.y * v.y + v.z * v.z + v.w * v.w;

#pragma unroll
    for (int off = 16; off; off >>= 1) {
        s  += __shfl_xor_sync(0xffffffffu, s, off);
        ss += __shfl_xor_sync(0xffffffffu, ss, off);
    }
    __shared__ float red[18];
    const int w = tid >> 5, lane = tid & 31;
    if (lane == 0) { red[w] = s; red[8 + w] = ss; }
    __syncthreads();
    if (tid == 0) {
        float ts = 0.f, tss = 0.f;
#pragma unroll
        for (int i = 0; i < 8; i++) { ts += red[i]; tss += red[8 + i]; }
        red[16] = ts * (1.f / DIM);
        red[17] = tss * (1.f / DIM);
    }
    __syncthreads();
    const float mean = red[16];
    const float var  = red[17] - mean * mean;
    const float rstd = rsqrtf(var + 1e-5f);

    const int cidx = tid * 4;
    float4 g  = *(const float4*)(gamma + cidx);
    float4 bb = *(const float4*)(beta + cidx);
    float4 ov;
    ov.x = (v.x - mean) * rstd * g.x + bb.x;
    ov.y = (v.y - mean) * rstd * g.y + bb.y;
    ov.z = (v.z - mean) * rstd * g.z + bb.z;
    ov.w = (v.w - mean) * rstd * g.w + bb.w;
    *(float4*)(out + (size_t)row * DIM + cidx) = ov;
}

// ---------------------------------------------------------------------------
extern "C" void kernel_launch(void* const* d_in, const int* in_sizes, int n_in,
                              void* d_out, int out_size)
{
    (void)in_sizes; (void)n_in; (void)out_size;
    const float* x     = (const float*)d_in[0];
    const float* w_qkv = (const float*)d_in[1];
    const float* w_out = (const float*)d_in[2];
    const float* b_out = (const float*)d_in[3];
    const float* gamma = (const float*)d_in[4];
    const float* beta  = (const float*)d_in[5];
    float* out = (float*)d_out;

    float *res;
    __nv_bfloat16 *ahi, *alo, *bhi, *blo, *qhi, *qlo, *khi, *klo, *vthi, *vtlo;
    cudaGetSymbolAddress((void**)&res, g_res);
    cudaGetSymbolAddress((void**)&ahi, g_ahi);
    cudaGetSymbolAddress((void**)&alo, g_alo);
    cudaGetSymbolAddress((void**)&bhi, g_bhi);
    cudaGetSymbolAddress((void**)&blo, g_blo);
    cudaGetSymbolAddress((void**)&qhi, g_qhi);
    cudaGetSymbolAddress((void**)&qlo, g_qlo);
    cudaGetSymbolAddress((void**)&khi, g_khi);
    cudaGetSymbolAddress((void**)&klo, g_klo);
    cudaGetSymbolAddress((void**)&vthi, g_vthi);
    cudaGetSymbolAddress((void**)&vtlo, g_vtlo);

    cudaFuncSetAttribute(gemm_mma, cudaFuncAttributeMaxDynamicSharedMemorySize, GEMM_SMEM);
    cudaFuncSetAttribute(attn_mma, cudaFuncAttributeMaxDynamicSharedMemorySize, AT_SMEM);

    // 0) x -> bf16 hi/lo ; w_qkv -> transposed hi/lo
    split_fp32<<<(ROWS * DIM / 4 + 255) / 256, 256>>>(x, ahi, alo, ROWS * DIM / 4);
    tsplit<<<dim3(QKV_N / 32, DIM / 32), dim3(32, 8)>>>(w_qkv, bhi, blo, DIM, QKV_N);

    // 1) QKV projection with fused q/k/v split epilogue
    gemm_mma<<<dim3(QKV_N / BN, ROWS / BM), 512, GEMM_SMEM>>>(
        ahi, alo, bhi, blo, nullptr, DIM, QKV_N, nullptr, nullptr,
        1, qhi, qlo, khi, klo, vthi, vtlo);

    // 2) flash attention -> bf16 hi/lo (reuses ahi/alo)
    attn_mma<<<dim3(SEQ / 128, BATCH * HEADS), 256, AT_SMEM>>>(
        qhi, qlo, khi, klo, vthi, vtlo, ahi, alo);

    // 3) out projection + bias + residual
    tsplit<<<dim3(DIM / 32, DIM / 32), dim3(32, 8)>>>(w_out, bhi, blo, DIM, DIM);
    gemm_mma<<<dim3(DIM / BN, ROWS / BM), 512, GEMM_SMEM>>>(
        ahi, alo, bhi, blo, res, DIM, DIM, b_out, x,
        0, nullptr, nullptr, nullptr, nullptr, nullptr, nullptr);

    // 4) LayerNorm
    ln_kernel<<<ROWS, 256>>>(res, gamma, beta, out);
}

// round 17
// speedup vs baseline: 1.5385x; 1.5385x over previous
#include <cuda_runtime.h>
#include <cuda_bf16.h>
#include <math.h>
#include <stdint.h>

#define HEADS    16
#define HEAD_DIM 64
#define DIM      1024
#define INNER    1024
#define BATCH    2
#define SEQ      2048
#define ROWS     4096
#define QKV_N    3072

// ---------------- scratch (no allocs allowed) ----------------
__device__ float         g_res[(size_t)ROWS * DIM];
__device__ __nv_bfloat16 g_ahi[(size_t)ROWS * DIM];
__device__ __nv_bfloat16 g_alo[(size_t)ROWS * DIM];
__device__ __nv_bfloat16 g_bhi[(size_t)QKV_N * DIM];
__device__ __nv_bfloat16 g_blo[(size_t)QKV_N * DIM];
__device__ __nv_bfloat16 g_qhi[(size_t)ROWS * DIM];
__device__ __nv_bfloat16 g_qlo[(size_t)ROWS * DIM];
__device__ __nv_bfloat16 g_khi[(size_t)ROWS * DIM];
__device__ __nv_bfloat16 g_klo[(size_t)ROWS * DIM];
__device__ __nv_bfloat16 g_vthi[(size_t)ROWS * DIM];
__device__ __nv_bfloat16 g_vtlo[(size_t)ROWS * DIM];

// ---------------- PTX helpers ----------------
__device__ __forceinline__ uint32_t smem_u32(const void* p) {
    uint32_t a;
    asm("{ .reg .u64 t; cvta.to.shared.u64 t, %1; cvt.u32.u64 %0, t; }" : "=r"(a) : "l"(p));
    return a;
}
__device__ __forceinline__ void cp16(uint32_t s, const void* g) {
    asm volatile("cp.async.cg.shared.global [%0], [%1], 16;" :: "r"(s), "l"(g));
}
#define CP_COMMIT() asm volatile("cp.async.commit_group;" ::: "memory")
#define CP_WAIT(n)  asm volatile("cp.async.wait_group %0;" :: "n"(n) : "memory")

__device__ __forceinline__ void ldsm4(uint32_t& r0, uint32_t& r1, uint32_t& r2, uint32_t& r3,
                                      uint32_t a) {
    asm volatile("ldmatrix.sync.aligned.m8n8.x4.shared.b16 {%0,%1,%2,%3}, [%4];"
                 : "=r"(r0), "=r"(r1), "=r"(r2), "=r"(r3) : "r"(a));
}
__device__ __forceinline__ void mma16816(float* d, const uint32_t* a, uint32_t b0, uint32_t b1) {
    asm volatile(
        "mma.sync.aligned.m16n8k16.row.col.f32.bf16.bf16.f32 "
        "{%0,%1,%2,%3}, {%4,%5,%6,%7}, {%8,%9}, {%0,%1,%2,%3};"
        : "+f"(d[0]), "+f"(d[1]), "+f"(d[2]), "+f"(d[3])
        : "r"(a[0]), "r"(a[1]), "r"(a[2]), "r"(a[3]), "r"(b0), "r"(b1));
}
__device__ __forceinline__ void split2(float a, float b, uint32_t& hi, uint32_t& lo) {
    __nv_bfloat16 ha = __float2bfloat16(a), hb = __float2bfloat16(b);
    __nv_bfloat162 H; H.x = ha; H.y = hb;
    __nv_bfloat162 L;
    L.x = __float2bfloat16(a - __bfloat162float(ha));
    L.y = __float2bfloat16(b - __bfloat162float(hb));
    hi = *(uint32_t*)&H;
    lo = *(uint32_t*)&L;
}

// ---------------------------------------------------------------------------
// Prep kernels
// ---------------------------------------------------------------------------
__global__ __launch_bounds__(256) void split_fp32(
    const float* __restrict__ X, __nv_bfloat16* __restrict__ H,
    __nv_bfloat16* __restrict__ L, int n4)
{
    int i = blockIdx.x * 256 + threadIdx.x;
    if (i >= n4) return;
    float4 v = ((const float4*)X)[i];
    union { __nv_bfloat16 b[4]; uint2 u; } ph, pl;
    float f[4] = {v.x, v.y, v.z, v.w};
#pragma unroll
    for (int j = 0; j < 4; j++) {
        __nv_bfloat16 h = __float2bfloat16(f[j]);
        ph.b[j] = h;
        pl.b[j] = __float2bfloat16(f[j] - __bfloat162float(h));
    }
    ((uint2*)H)[i] = ph.u;
    ((uint2*)L)[i] = pl.u;
}

__global__ void tsplit(const float* __restrict__ W, __nv_bfloat16* __restrict__ TH,
                       __nv_bfloat16* __restrict__ TL, int K, int N)
{
    __shared__ float t[32][33];
    int n0 = blockIdx.x * 32, k0 = blockIdx.y * 32;
    int tx = threadIdx.x, ty = threadIdx.y;
#pragma unroll
    for (int i = 0; i < 32; i += 8)
        t[ty + i][tx] = W[(size_t)(k0 + ty + i) * N + n0 + tx];
    __syncthreads();
#pragma unroll
    for (int i = 0; i < 32; i += 8) {
        float v = t[tx][ty + i];
        __nv_bfloat16 h = __float2bfloat16(v);
        size_t oidx = (size_t)(n0 + ty + i) * K + k0 + tx;
        TH[oidx] = h;
        TL[oidx] = __float2bfloat16(v - __bfloat162float(h));
    }
}

// ---------------------------------------------------------------------------
// mma.sync bf16x3 GEMM. 512 threads, 16 warps of 32x32 (4x4 grid).
// 3-stage cp.async, ONE barrier per chunk. Natural regs (no min-blocks bound).
// mode 0: fp32 C (+bias +resid). mode 1: fused qkv split epilogue.
// ---------------------------------------------------------------------------
#define BM 128
#define BN 128
#define BKC 32
#define ROWB 80
#define TILE_BYTES (128 * ROWB)
#define STAGE_BYTES (4 * TILE_BYTES)          // 40960
#define GEMM_SMEM (3 * STAGE_BYTES + 256)     // 123136

__global__ __launch_bounds__(512) void gemm_mma(
    const __nv_bfloat16* __restrict__ Ahi, const __nv_bfloat16* __restrict__ Alo,
    const __nv_bfloat16* __restrict__ Bhi, const __nv_bfloat16* __restrict__ Blo,
    float* __restrict__ C, int K, int N,
    const float* __restrict__ bias, const float* __restrict__ resid,
    int mode,
    __nv_bfloat16* __restrict__ qhi, __nv_bfloat16* __restrict__ qlo,
    __nv_bfloat16* __restrict__ khi, __nv_bfloat16* __restrict__ klo,
    __nv_bfloat16* __restrict__ vthi, __nv_bfloat16* __restrict__ vtlo)
{
    extern __shared__ char dsm[];
    const int tid  = threadIdx.x;
    const int wid  = tid >> 5;
    const int lane = tid & 31;
    const int bm   = blockIdx.y * BM;
    const int bn   = blockIdx.x * BN;

    const uint32_t sb = (smem_u32(dsm) + 127u) & ~127u;

    // loader: 512 chunks per tile, 1 chunk per thread per tile
    const int r0 = tid >> 2, c0 = tid & 3;
    const uint32_t s0 = r0 * ROWB + c0 * 16;
    const size_t gA0 = (size_t)(bm + r0) * K + c0 * 8;
    const size_t gB0 = (size_t)(bn + r0) * K + c0 * 8;

    float acc[2][4][4];
#pragma unroll
    for (int i = 0; i < 2; i++)
#pragma unroll
        for (int j = 0; j < 4; j++)
#pragma unroll
            for (int q = 0; q < 4; q++) acc[i][j][q] = 0.f;

    const int nch = K / BKC;

#define LOAD_STAGE(kc, st) do {                                                 \
    uint32_t s = sb + (uint32_t)(st) * STAGE_BYTES;                             \
    int ko = (kc) * BKC;                                                        \
    cp16(s + s0,                  Ahi + gA0 + ko);                              \
    cp16(s + TILE_BYTES + s0,     Alo + gA0 + ko);                              \
    cp16(s + 2 * TILE_BYTES + s0, Bhi + gB0 + ko);                              \
    cp16(s + 3 * TILE_BYTES + s0, Blo + gB0 + ko);                              \
} while (0)

    LOAD_STAGE(0, 0);
    CP_COMMIT();
    if (nch > 1) { LOAD_STAGE(1, 1); CP_COMMIT(); }

    const int wm = (wid & 3) * 32;        // 4x4 warp grid
    const int wn = (wid >> 2) * 32;

    const uint32_t a_off = (uint32_t)(wm + (lane & 15)) * ROWB + ((lane >> 4) << 3) * 2;
    const uint32_t b_off = (uint32_t)(wn + (lane & 7) + ((lane >> 4) << 3)) * ROWB +
                           (((lane >> 3) & 1) << 3) * 2;

    for (int kc = 0; kc < nch; kc++) {
        const int st = kc % 3;
        if (kc + 1 < nch) { CP_WAIT(1); } else { CP_WAIT(0); }
        __syncthreads();
        if (kc + 2 < nch) { LOAD_STAGE(kc + 2, (kc + 2) % 3); CP_COMMIT(); }

        const uint32_t sAhi = sb + (uint32_t)st * STAGE_BYTES;
        const uint32_t sAlo = sAhi + TILE_BYTES;
        const uint32_t sBhi = sAhi + 2 * TILE_BYTES;
        const uint32_t sBlo = sAhi + 3 * TILE_BYTES;

#pragma unroll
        for (int ks = 0; ks < 2; ks++) {
            const uint32_t kb = ks * 32;
            uint32_t ah[2][4], bh[8];
#pragma unroll
            for (int mf = 0; mf < 2; mf++)
                ldsm4(ah[mf][0], ah[mf][1], ah[mf][2], ah[mf][3],
                      sAhi + a_off + kb + mf * (16 * ROWB));
            ldsm4(bh[0], bh[1], bh[2], bh[3], sBhi + b_off + kb);
            ldsm4(bh[4], bh[5], bh[6], bh[7], sBhi + b_off + kb + 16 * ROWB);
#pragma unroll
            for (int mf = 0; mf < 2; mf++)
#pragma unroll
                for (int nf = 0; nf < 4; nf++)
                    mma16816(acc[mf][nf], ah[mf], bh[nf * 2], bh[nf * 2 + 1]);
            {
                uint32_t al[2][4];
#pragma unroll
                for (int mf = 0; mf < 2; mf++)
                    ldsm4(al[mf][0], al[mf][1], al[mf][2], al[mf][3],
                          sAlo + a_off + kb + mf * (16 * ROWB));
#pragma unroll
                for (int mf = 0; mf < 2; mf++)
#pragma unroll
                    for (int nf = 0; nf < 4; nf++)
                        mma16816(acc[mf][nf], al[mf], bh[nf * 2], bh[nf * 2 + 1]);
            }
            {
                uint32_t bl[8];
                ldsm4(bl[0], bl[1], bl[2], bl[3], sBlo + b_off + kb);
                ldsm4(bl[4], bl[5], bl[6], bl[7], sBlo + b_off + kb + 16 * ROWB);
#pragma unroll
                for (int mf = 0; mf < 2; mf++)
#pragma unroll
                    for (int nf = 0; nf < 4; nf++)
                        mma16816(acc[mf][nf], ah[mf], bl[nf * 2], bl[nf * 2 + 1]);
            }
        }
    }

    // ---------------- epilogue ----------------
    if (mode == 0) {
#pragma unroll
        for (int mf = 0; mf < 2; mf++) {
            const int row = bm + wm + mf * 16 + (lane >> 2);
#pragma unroll
            for (int nf = 0; nf < 4; nf++) {
                const int col = bn + wn + nf * 8 + 2 * (lane & 3);
                float2 v0 = make_float2(acc[mf][nf][0], acc[mf][nf][1]);
                float2 v1 = make_float2(acc[mf][nf][2], acc[mf][nf][3]);
                if (bias) {
                    float2 bi = *(const float2*)(bias + col);
                    v0.x += bi.x; v0.y += bi.y;
                    v1.x += bi.x; v1.y += bi.y;
                }
                if (resid) {
                    float2 ra = *(const float2*)(resid + (size_t)row * N + col);
                    float2 rb = *(const float2*)(resid + (size_t)(row + 8) * N + col);
                    v0.x += ra.x; v0.y += ra.y;
                    v1.x += rb.x; v1.y += rb.y;
                }
                *(float2*)(C + (size_t)row * N + col) = v0;
                *(float2*)(C + (size_t)(row + 8) * N + col) = v1;
            }
        }
    } else if (bn < 1024) {
        // q: scale 0.125, split -> [row][dim]
#pragma unroll
        for (int mf = 0; mf < 2; mf++) {
            const int rowa = bm + wm + mf * 16 + (lane >> 2);
#pragma unroll
            for (int nf = 0; nf < 4; nf++) {
                const int col = bn + wn + nf * 8 + 2 * (lane & 3);
                uint32_t hh, ll;
                split2(acc[mf][nf][0] * 0.125f, acc[mf][nf][1] * 0.125f, hh, ll);
                *(uint32_t*)(qhi + (size_t)rowa * DIM + col) = hh;
                *(uint32_t*)(qlo + (size_t)rowa * DIM + col) = ll;
                split2(acc[mf][nf][2] * 0.125f, acc[mf][nf][3] * 0.125f, hh, ll);
                *(uint32_t*)(qhi + (size_t)(rowa + 8) * DIM + col) = hh;
                *(uint32_t*)(qlo + (size_t)(rowa + 8) * DIM + col) = ll;
            }
        }
    } else if (bn < 2048) {
        // k: split -> [bh][key][d]
#pragma unroll
        for (int mf = 0; mf < 2; mf++) {
            const int rowa = bm + wm + mf * 16 + (lane >> 2);
            const int b0b = rowa >> 11;
#pragma unroll
            for (int nf = 0; nf < 4; nf++) {
                const int ck = bn - 1024 + wn + nf * 8 + 2 * (lane & 3);
                const int hK = ck >> 6, dK = ck & 63;
                size_t o0 = ((size_t)(b0b * HEADS + hK) << 17) + (size_t)(rowa & 2047) * 64 + dK;
                size_t o1 = ((size_t)(b0b * HEADS + hK) << 17) + (size_t)((rowa + 8) & 2047) * 64 + dK;
                uint32_t hh, ll;
                split2(acc[mf][nf][0], acc[mf][nf][1], hh, ll);
                *(uint32_t*)(khi + o0) = hh;
                *(uint32_t*)(klo + o0) = ll;
                split2(acc[mf][nf][2], acc[mf][nf][3], hh, ll);
                *(uint32_t*)(khi + o1) = hh;
                *(uint32_t*)(klo + o1) = ll;
            }
        }
    } else {
        // v: smem transpose, split -> [bh][d][key]
        float* esm = (float*)(dsm + (sb - smem_u32(dsm)));   // [128][129]
        __syncthreads();
#pragma unroll
        for (int mf = 0; mf < 2; mf++) {
            const int rl = wm + mf * 16 + (lane >> 2);
#pragma unroll
            for (int nf = 0; nf < 4; nf++) {
                const int cl = wn + nf * 8 + 2 * (lane & 3);
                esm[rl * 129 + cl]       = acc[mf][nf][0];
                esm[rl * 129 + cl + 1]   = acc[mf][nf][1];
                esm[(rl + 8) * 129 + cl]     = acc[mf][nf][2];
                esm[(rl + 8) * 129 + cl + 1] = acc[mf][nf][3];
            }
        }
        __syncthreads();
        const int bb   = bm >> 11;
        const int key0 = bm & 2047;
        const int colc = tid & 127;            // output column (head-dim pair)
        const int q4   = tid >> 7;             // key quarter (32 keys)
        const int dd   = colc & 63;
        const int hg   = ((bn - 2048) >> 6) + (colc >> 6);
        const size_t ob = ((size_t)(bb * HEADS + hg) << 17) + (size_t)dd * SEQ +
                          key0 + q4 * 32;
#pragma unroll
        for (int k = 0; k < 32; k += 2) {
            float v0 = esm[(q4 * 32 + k) * 129 + colc];
            float v1 = esm[(q4 * 32 + k + 1) * 129 + colc];
            uint32_t hh, ll;
            split2(v0, v1, hh, ll);
            *(uint32_t*)(vthi + ob + k) = hh;
            *(uint32_t*)(vtlo + ob + k) = ll;
        }
    }
#undef LOAD_STAGE
}

// ---------------------------------------------------------------------------
// Flash attention, mma.sync bf16 split. 2-stage, 2 barriers/tile, 2 CTAs/SM.
// ---------------------------------------------------------------------------
#define AT_ROWB  144
#define AT_TILE  (64 * AT_ROWB)       // 9216
#define AT_STAGE (4 * AT_TILE)        // 36864
#define AT_SMEM  (2 * AT_STAGE + 128) // 73856

__global__ __launch_bounds__(256, 2) void attn_mma(
    const __nv_bfloat16* __restrict__ qhi, const __nv_bfloat16* __restrict__ qlo,
    const __nv_bfloat16* __restrict__ khi, const __nv_bfloat16* __restrict__ klo,
    const __nv_bfloat16* __restrict__ vthi, const __nv_bfloat16* __restrict__ vtlo,
    __nv_bfloat16* __restrict__ ohi, __nv_bfloat16* __restrict__ olo)
{
    extern __shared__ char dsm[];
    const int tid  = threadIdx.x;
    const int wid  = tid >> 5;
    const int lane = tid & 31;
    const int g    = lane >> 2;
    const int t    = lane & 3;
    const int bh   = blockIdx.y;
    const int b    = bh >> 4;
    const int h    = bh & 15;
    const int row0 = b * SEQ + blockIdx.x * 128;

    const uint32_t sb = (smem_u32(dsm) + 127u) & ~127u;

    // ---- stage Q, load frags ----
    {
        const uint32_t sQhi = sb, sQlo = sb + 128 * AT_ROWB;
#pragma unroll
        for (int i = 0; i < 4; i++) {
            int c = tid + i * 256;
            int r = c >> 3, ch = c & 7;
            size_t gq = (size_t)(row0 + r) * DIM + h * 64 + ch * 8;
            cp16(sQhi + r * AT_ROWB + ch * 16, qhi + gq);
            cp16(sQlo + r * AT_ROWB + ch * 16, qlo + gq);
        }
        CP_COMMIT();
        CP_WAIT(0);
        __syncthreads();
    }
    uint32_t qh[4][4], ql[4][4];
    {
        const uint32_t qoff = (uint32_t)(wid * 16 + (lane & 15)) * AT_ROWB +
                              ((lane >> 4) << 3) * 2;
#pragma unroll
        for (int ks = 0; ks < 4; ks++) {
            ldsm4(qh[ks][0], qh[ks][1], qh[ks][2], qh[ks][3], sb + qoff + ks * 32);
            ldsm4(ql[ks][0], ql[ks][1], ql[ks][2], ql[ks][3],
                  sb + 128 * AT_ROWB + qoff + ks * 32);
        }
    }
    __syncthreads();

    float o[8][4];
#pragma unroll
    for (int i = 0; i < 8; i++)
#pragma unroll
        for (int j = 0; j < 4; j++) o[i][j] = 0.f;
    float m0 = -1e30f, m1 = -1e30f, l0 = 0.f, l1 = 0.f;

    const __nv_bfloat16* kb_hi = khi + ((size_t)bh << 17);
    const __nv_bfloat16* kb_lo = klo + ((size_t)bh << 17);
    const __nv_bfloat16* vb_hi = vthi + ((size_t)bh << 17);
    const __nv_bfloat16* vb_lo = vtlo + ((size_t)bh << 17);

#define LOADKV(kt, st) do {                                                     \
    uint32_t s = sb + (uint32_t)(st) * AT_STAGE;                                \
    int key0 = (kt) * 64;                                                       \
    _Pragma("unroll")                                                           \
    for (int i = 0; i < 2; i++) {                                               \
        int c = tid + i * 256;                                                  \
        int r = c >> 3, ch = c & 7;                                             \
        uint32_t so = r * AT_ROWB + ch * 16;                                    \
        cp16(s + so,               kb_hi + (size_t)(key0 + r) * 64 + ch * 8);   \
        cp16(s + AT_TILE + so,     kb_lo + (size_t)(key0 + r) * 64 + ch * 8);   \
        cp16(s + 2 * AT_TILE + so, vb_hi + (size_t)r * SEQ + key0 + ch * 8);    \
        cp16(s + 3 * AT_TILE + so, vb_lo + (size_t)r * SEQ + key0 + ch * 8);    \
    }                                                                           \
} while (0)

    const uint32_t boff = (uint32_t)((lane & 7) + ((lane >> 4) << 3)) * AT_ROWB +
                          (((lane >> 3) & 1) << 3) * 2;

    LOADKV(0, 0);
    CP_COMMIT();

    const int NT = SEQ / 64;
    for (int kt = 0; kt < NT; kt++) {
        const int st = kt & 1;
        __syncthreads();                 // readers of stage st^1 finished
        if (kt + 1 < NT) {
            LOADKV(kt + 1, st ^ 1);
            CP_COMMIT();
            CP_WAIT(1);
        } else {
            CP_WAIT(0);
        }
        __syncthreads();                 // stage st ready

        const uint32_t sKh = sb + (uint32_t)st * AT_STAGE;
        const uint32_t sKl = sKh + AT_TILE;
        const uint32_t sVh = sKh + 2 * AT_TILE;
        const uint32_t sVl = sKh + 3 * AT_TILE;

        // ---- S = Q K^T (3-term split, JIT frags) ----
        float s[8][4];
#pragma unroll
        for (int i = 0; i < 8; i++)
#pragma unroll
            for (int j = 0; j < 4; j++) s[i][j] = 0.f;

#pragma unroll
        for (int ks = 0; ks < 4; ks++) {
#pragma unroll
            for (int kb = 0; kb < 4; kb++) {
                uint32_t kh4[4];
                ldsm4(kh4[0], kh4[1], kh4[2], kh4[3],
                      sKh + boff + kb * (16 * AT_ROWB) + ks * 32);
                mma16816(s[2 * kb],     qh[ks], kh4[0], kh4[1]);
                mma16816(s[2 * kb + 1], qh[ks], kh4[2], kh4[3]);
                mma16816(s[2 * kb],     ql[ks], kh4[0], kh4[1]);
                mma16816(s[2 * kb + 1], ql[ks], kh4[2], kh4[3]);
                uint32_t kl4[4];
                ldsm4(kl4[0], kl4[1], kl4[2], kl4[3],
                      sKl + boff + kb * (16 * AT_ROWB) + ks * 32);
                mma16816(s[2 * kb],     qh[ks], kl4[0], kl4[1]);
                mma16816(s[2 * kb + 1], qh[ks], kl4[2], kl4[3]);
            }
        }

        // ---- online softmax ----
        float mx0 = -1e30f, mx1 = -1e30f;
#pragma unroll
        for (int nf = 0; nf < 8; nf++) {
            mx0 = fmaxf(mx0, fmaxf(s[nf][0], s[nf][1]));
            mx1 = fmaxf(mx1, fmaxf(s[nf][2], s[nf][3]));
        }
        mx0 = fmaxf(mx0, __shfl_xor_sync(0xffffffffu, mx0, 1));
        mx0 = fmaxf(mx0, __shfl_xor_sync(0xffffffffu, mx0, 2));
        mx1 = fmaxf(mx1, __shfl_xor_sync(0xffffffffu, mx1, 1));
        mx1 = fmaxf(mx1, __shfl_xor_sync(0xffffffffu, mx1, 2));
        const float nm0 = fmaxf(m0, mx0), nm1 = fmaxf(m1, mx1);
        const float c0 = __expf(m0 - nm0), c1 = __expf(m1 - nm1);
#pragma unroll
        for (int nf = 0; nf < 8; nf++) {
            o[nf][0] *= c0; o[nf][1] *= c0;
            o[nf][2] *= c1; o[nf][3] *= c1;
        }
        float rs0 = 0.f, rs1 = 0.f;
#pragma unroll
        for (int nf = 0; nf < 8; nf++) {
            s[nf][0] = __expf(s[nf][0] - nm0); rs0 += s[nf][0];
            s[nf][1] = __expf(s[nf][1] - nm0); rs0 += s[nf][1];
            s[nf][2] = __expf(s[nf][2] - nm1); rs1 += s[nf][2];
            s[nf][3] = __expf(s[nf][3] - nm1); rs1 += s[nf][3];
        }
        rs0 += __shfl_xor_sync(0xffffffffu, rs0, 1);
        rs0 += __shfl_xor_sync(0xffffffffu, rs0, 2);
        rs1 += __shfl_xor_sync(0xffffffffu, rs1, 1);
        rs1 += __shfl_xor_sync(0xffffffffu, rs1, 2);
        l0 = l0 * c0 + rs0;
        l1 = l1 * c1 + rs1;
        m0 = nm0; m1 = nm1;

        // ---- O += P V (3-term split, JIT frags) ----
#pragma unroll
        for (int kk = 0; kk < 4; kk++) {
            uint32_t ph[4], pl[4];
            split2(s[2 * kk][0],     s[2 * kk][1],     ph[0], pl[0]);
            split2(s[2 * kk][2],     s[2 * kk][3],     ph[1], pl[1]);
            split2(s[2 * kk + 1][0], s[2 * kk + 1][1], ph[2], pl[2]);
            split2(s[2 * kk + 1][2], s[2 * kk + 1][3], ph[3], pl[3]);

#pragma unroll
            for (int db = 0; db < 4; db++) {
                uint32_t vh4[4];
                ldsm4(vh4[0], vh4[1], vh4[2], vh4[3],
                      sVh + boff + db * (16 * AT_ROWB) + kk * 32);
                mma16816(o[2 * db],     ph, vh4[0], vh4[1]);
                mma16816(o[2 * db + 1], ph, vh4[2], vh4[3]);
                mma16816(o[2 * db],     pl, vh4[0], vh4[1]);
                mma16816(o[2 * db + 1], pl, vh4[2], vh4[3]);
                uint32_t vl4[4];
                ldsm4(vl4[0], vl4[1], vl4[2], vl4[3],
                      sVl + boff + db * (16 * AT_ROWB) + kk * 32);
                mma16816(o[2 * db],     ph, vl4[0], vl4[1]);
                mma16816(o[2 * db + 1], ph, vl4[2], vl4[3]);
            }
        }
    }
#undef LOADKV

    // ---- epilogue ----
    const float inv0 = 1.f / l0, inv1 = 1.f / l1;
    const int row_a = row0 + wid * 16 + g;
    const int row_b = row_a + 8;
#pragma unroll
    for (int nf = 0; nf < 8; nf++) {
        const int col = h * 64 + nf * 8 + 2 * t;
        uint32_t hh, ll;
        split2(o[nf][0] * inv0, o[nf][1] * inv0, hh, ll);
        *(uint32_t*)(ohi + (size_t)row_a * DIM + col) = hh;
        *(uint32_t*)(olo + (size_t)row_a * DIM + col) = ll;
        split2(o[nf][2] * inv1, o[nf][3] * inv1, hh, ll);
        *(uint32_t*)(ohi + (size_t)row_b * DIM + col) = hh;
        *(uint32_t*)(olo + (size_t)row_b * DIM + col) = ll;
    }
}

// ---------------------------------------------------------------------------
// LayerNorm
// ---------------------------------------------------------------------------
__global__ __launch_bounds__(256) void ln_kernel(
    const float* __restrict__ res, const float* __restrict__ gamma,
    const float* __restrict__ beta, float* __restrict__ out)
{
    const int row = blockIdx.x;
    const int tid = threadIdx.x;
    const float* rp = res + (size_t)row * DIM;

    float4 v = *(const float4*)(rp + tid * 4);
    float s  = v.x + v.y + v.z + v.w;
    float ss = v.x * v.x + v.y * v.y + v.z * v.z + v.w * v.w;

#pragma unroll
    for (int off = 16; off; off >>= 1) {
        s  += __shfl_xor_sync(0xffffffffu, s, off);
        ss += __shfl_xor_sync(0xffffffffu, ss, off);
    }
    __shared__ float red[18];
    const int w = tid >> 5, lane = tid & 31;
    if (lane == 0) { red[w] = s; red[8 + w] = ss; }
    __syncthreads();
    if (tid == 0) {
        float ts = 0.f, tss = 0.f;
#pragma unroll
        for (int i = 0; i < 8; i++) { ts += red[i]; tss += red[8 + i]; }
        red[16] = ts * (1.f / DIM);
        red[17] = tss * (1.f / DIM);
    }
    __syncthreads();
    const float mean = red[16];
    const float var  = red[17] - mean * mean;
    const float rstd = rsqrtf(var + 1e-5f);

    const int cidx = tid * 4;
    float4 g  = *(const float4*)(gamma + cidx);
    float4 bb = *(const float4*)(beta + cidx);
    float4 ov;
    ov.x = (v.x - mean) * rstd * g.x + bb.x;
    ov.y = (v.y - mean) * rstd * g.y + bb.y;
    ov.z = (v.z - mean) * rstd * g.z + bb.z;
    ov.w = (v.w - mean) * rstd * g.w + bb.w;
    *(float4*)(out + (size_t)row * DIM + cidx) = ov;
}

// ---------------------------------------------------------------------------
extern "C" void kernel_launch(void* const* d_in, const int* in_sizes, int n_in,
                              void* d_out, int out_size)
{
    (void)in_sizes; (void)n_in; (void)out_size;
    const float* x     = (const float*)d_in[0];
    const float* w_qkv = (const float*)d_in[1];
    const float* w_out = (const float*)d_in[2];
    const float* b_out = (const float*)d_in[3];
    const float* gamma = (const float*)d_in[4];
    const float* beta  = (const float*)d_in[5];
    float* out = (float*)d_out;

    float *res;
    __nv_bfloat16 *ahi, *alo, *bhi, *blo, *qhi, *qlo, *khi, *klo, *vthi, *vtlo;
    cudaGetSymbolAddress((void**)&res, g_res);
    cudaGetSymbolAddress((void**)&ahi, g_ahi);
    cudaGetSymbolAddress((void**)&alo, g_alo);
    cudaGetSymbolAddress((void**)&bhi, g_bhi);
    cudaGetSymbolAddress((void**)&blo, g_blo);
    cudaGetSymbolAddress((void**)&qhi, g_qhi);
    cudaGetSymbolAddress((void**)&qlo, g_qlo);
    cudaGetSymbolAddress((void**)&khi, g_khi);
    cudaGetSymbolAddress((void**)&klo, g_klo);
    cudaGetSymbolAddress((void**)&vthi, g_vthi);
    cudaGetSymbolAddress((void**)&vtlo, g_vtlo);

    cudaFuncSetAttribute(gemm_mma, cudaFuncAttributeMaxDynamicSharedMemorySize, GEMM_SMEM);
    cudaFuncSetAttribute(attn_mma, cudaFuncAttributeMaxDynamicSharedMemorySize, AT_SMEM);

    // 0) x -> bf16 hi/lo ; w_qkv -> transposed hi/lo
    split_fp32<<<(ROWS * DIM / 4 + 255) / 256, 256>>>(x, ahi, alo, ROWS * DIM / 4);
    tsplit<<<dim3(QKV_N / 32, DIM / 32), dim3(32, 8)>>>(w_qkv, bhi, blo, DIM, QKV_N);

    // 1) QKV projection with fused q/k/v split epilogue
    gemm_mma<<<dim3(QKV_N / BN, ROWS / BM), 512, GEMM_SMEM>>>(
        ahi, alo, bhi, blo, nullptr, DIM, QKV_N, nullptr, nullptr,
        1, qhi, qlo, khi, klo, vthi, vtlo);

    // 2) flash attention -> bf16 hi/lo (reuses ahi/alo)
    attn_mma<<<dim3(SEQ / 128, BATCH * HEADS), 256, AT_SMEM>>>(
        qhi, qlo, khi, klo, vthi, vtlo, ahi, alo);

    // 3) out projection + bias + residual
    tsplit<<<dim3(DIM / 32, DIM / 32), dim3(32, 8)>>>(w_out, bhi, blo, DIM, DIM);
    gemm_mma<<<dim3(DIM / BN, ROWS / BM), 512, GEMM_SMEM>>>(
        ahi, alo, bhi, blo, res, DIM, DIM, b_out, x,
        0, nullptr, nullptr, nullptr, nullptr, nullptr, nullptr);

    // 4) LayerNorm
    ln_kernel<<<ROWS, 256>>>(res, gamma, beta, out);
}